// round 3
// baseline (speedup 1.0000x reference)
#include <cuda_runtime.h>

// Problem dims (fixed)
#define Bb   2
#define Ss   2048
#define Dd   1024
#define Hh   16
#define KVh  4
#define QKBd 16
#define VBd  32
#define MROWS (Bb*Ss)          // 4096
#define HVB   (Hh*VBd)         // 512

typedef unsigned long long u64;

// ---------------- f32x2 packed-math helpers (Blackwell FP32x2 pipe) ----------
__device__ __forceinline__ u64 ffma2(u64 a, u64 b, u64 c) {
    u64 d; asm("fma.rn.f32x2 %0, %1, %2, %3;" : "=l"(d) : "l"(a), "l"(b), "l"(c));
    return d;
}
__device__ __forceinline__ u64 fmul2(u64 a, u64 b) {
    u64 d; asm("mul.rn.f32x2 %0, %1, %2;" : "=l"(d) : "l"(a), "l"(b));
    return d;
}
__device__ __forceinline__ u64 fadd2(u64 a, u64 b) {
    u64 d; asm("add.rn.f32x2 %0, %1, %2;" : "=l"(d) : "l"(a), "l"(b));
    return d;
}
__device__ __forceinline__ u64 pack2(float x, float y) {
    u64 r; asm("mov.b64 %0, {%1, %2};" : "=l"(r) : "f"(x), "f"(y)); return r;
}
__device__ __forceinline__ float2 unpk2(u64 v) {
    float2 r; asm("mov.b64 {%0, %1}, %2;" : "=f"(r.x), "=f"(r.y) : "l"(v)); return r;
}

// ---------------- scratch (static device arrays; no allocation) -------------
__device__ __align__(16) float g_pq[Bb*Hh*Ss*QKBd];    // [(b*H+h)*S+s][16]
__device__ __align__(16) float g_pk[Bb*KVh*Ss*QKBd];   // [(b*KV+kv)*S+t][16]
__device__ __align__(16) float g_sk[Bb*KVh*Ss];        // row sums of pk
__device__ __align__(16) float g_pv[Bb*KVh*Ss*VBd];    // [(b*KV+kv)*S+t][32]
__device__ __align__(16) float g_vh[Bb*Ss*HVB];        // [b*S+s][h*32+j]
__device__ __align__(16) float g_bias[Dd];             // e0 @ Wo

__device__ __forceinline__ float sigmoidf_fast(float x) {
    return __fdividef(1.f, 1.f + __expf(-x));
}

// ---------------- Kernel 1: QKV projection GEMM + sigmoid --------------------
// C = sigmoid(A @ W); A = hidden [4096,1024]; W [1024,N]; scattered epilogue.
// 128x64 tile, BK=32, 256 threads, 8x4 per thread via FFMA2.
#define BSTR 68
__global__ __launch_bounds__(256) void proj_kernel(
    const float* __restrict__ A, const float* __restrict__ W, int N, int mode)
{
    __shared__ u64   As[32 * 128];   // duplicated (a,a) pairs, [k][m]
    __shared__ float Bs[32 * BSTR];  // [k][n], padded

    const int m0  = blockIdx.x * 128;
    const int n0  = blockIdx.y * 64;
    const int tid = threadIdx.x;
    const int tm  = tid >> 4;        // 0..15 -> rows tm*8..tm*8+7
    const int tn  = tid & 15;        // 0..15 -> cols tn*4..tn*4+3

    // fill assignments
    const int fm = tid >> 1;         // 0..127 (A rows)
    const int fk = (tid & 1) * 16;   // k part
    const int bk = tid >> 3;         // 0..31  (B k)
    const int jb = (tid & 7) * 8;    // B col part

    u64 acc[8][2];
#pragma unroll
    for (int i = 0; i < 8; ++i) { acc[i][0] = 0ULL; acc[i][1] = 0ULL; }

    for (int k0 = 0; k0 < Dd; k0 += 32) {
        // A fill (duplicated pairs, transposed)
        {
            const float* Ar = &A[(m0 + fm) * Dd + k0 + fk];
            float4 a0 = *(const float4*)(Ar + 0);
            float4 a1 = *(const float4*)(Ar + 4);
            float4 a2 = *(const float4*)(Ar + 8);
            float4 a3 = *(const float4*)(Ar + 12);
            float av[16] = {a0.x,a0.y,a0.z,a0.w, a1.x,a1.y,a1.z,a1.w,
                            a2.x,a2.y,a2.z,a2.w, a3.x,a3.y,a3.z,a3.w};
#pragma unroll
            for (int s = 0; s < 16; ++s)
                As[(fk + s) * 128 + fm] = pack2(av[s], av[s]);
        }
        // B fill
        {
            const float* Wr = &W[(k0 + bk) * N + n0 + jb];
            *(float4*)&Bs[bk * BSTR + jb]     = *(const float4*)(Wr + 0);
            *(float4*)&Bs[bk * BSTR + jb + 4] = *(const float4*)(Wr + 4);
        }
        __syncthreads();

#pragma unroll
        for (int k = 0; k < 32; ++k) {
            const ulonglong2* ap = (const ulonglong2*)&As[k * 128 + tm * 8];
            ulonglong2 a01 = ap[0], a23 = ap[1], a45 = ap[2], a67 = ap[3];
            ulonglong2 bv = *(const ulonglong2*)&Bs[k * BSTR + tn * 4];
            u64 ar[8] = {a01.x, a01.y, a23.x, a23.y, a45.x, a45.y, a67.x, a67.y};
#pragma unroll
            for (int i = 0; i < 8; ++i) {
                acc[i][0] = ffma2(ar[i], bv.x, acc[i][0]);
                acc[i][1] = ffma2(ar[i], bv.y, acc[i][1]);
            }
        }
        __syncthreads();
    }

    const int col0 = n0 + tn * 4;
#pragma unroll
    for (int i = 0; i < 8; ++i) {
        const int r  = m0 + tm * 8 + i;
        const int bb = r >> 11;
        const int ss = r & (Ss - 1);
        float2 p0 = unpk2(acc[i][0]);
        float2 p1 = unpk2(acc[i][1]);
        float4 sg;
        sg.x = sigmoidf_fast(p0.x);
        sg.y = sigmoidf_fast(p0.y);
        sg.z = sigmoidf_fast(p1.x);
        sg.w = sigmoidf_fast(p1.y);
        if (mode == 0) {
            const int h = col0 >> 4, d = col0 & 15;
            *(float4*)&g_pq[(((bb*Hh + h)*Ss) + ss)*QKBd + d] = sg;
        } else if (mode == 1) {
            const int kv = col0 >> 4, d = col0 & 15;
            *(float4*)&g_pk[(((bb*KVh + kv)*Ss) + ss)*QKBd + d] = sg;
        } else {
            const int kv = col0 >> 5, d = col0 & 31;
            *(float4*)&g_pv[(((bb*KVh + kv)*Ss) + ss)*VBd + d] = sg;
        }
    }
}

// ---------------- Kernel 1b: sk[t] = sum_d pk[t][d] --------------------------
__global__ void sk_kernel()
{
    const int idx = blockIdx.x * 256 + threadIdx.x;
    const float4* p = (const float4*)&g_pk[idx * QKBd];
    float4 a = p[0], b = p[1], c = p[2], d = p[3];
    g_sk[idx] = ((a.x + a.y) + (a.z + a.w)) + ((b.x + b.y) + (b.z + b.w))
              + ((c.x + c.y) + (c.z + c.w)) + ((d.x + d.y) + (d.z + d.w));
}

// ---------------- Kernel 1c: bias[d] = sum_j e0[j] * Wo[j][d] ----------------
__global__ void bias_kernel(const float* __restrict__ Wo, const float* __restrict__ e0)
{
    const int d = blockIdx.x * 256 + threadIdx.x;
    float s = 0.f;
    for (int j = 0; j < HVB; ++j)
        s = fmaf(e0[j], Wo[j * Dd + d], s);
    g_bias[d] = s;
}

// ---------------- Kernel 2: causal attention (f32x2) -------------------------
// logit(s,t) = 2*pq[s].pk[t] - sk[t]; w = exp(logit); vh = sum w*pv / sum w.
// Logits bounded in [-16,32] -> no max subtraction needed in fp32.
#define KSTR 20   // 16 data + sk + pad floats; 80B row = 16B aligned
#define VSTR 36   // 32 data + pad; 144B row = 16B aligned

__global__ __launch_bounds__(256) void attn_kernel()
{
    __shared__ float kx[64 * KSTR];
    __shared__ float vx[64 * VSTR];
    const int qt  = (Ss/64 - 1) - blockIdx.x;   // heavy tiles first
    const int h   = blockIdx.y;
    const int bb  = blockIdx.z;
    const int kvh = h >> 2;
    const int tid = threadIdx.x;
    const int ql  = tid >> 2;                   // local query 0..63
    const int sub = tid & 3;
    const int qg  = qt * 64 + ql;

    // packed query
    const ulonglong2* qp = (const ulonglong2*)&g_pq[((bb*Hh + h)*Ss + qg) * QKBd];
    ulonglong2 q01 = qp[0], q23 = qp[1], q45 = qp[2], q67 = qp[3];
    u64 q2[8] = {q01.x,q01.y,q23.x,q23.y,q45.x,q45.y,q67.x,q67.y};

    const float* __restrict__ pkb = &g_pk[(bb*KVh + kvh) * Ss * QKBd];
    const float* __restrict__ skb = &g_sk[(bb*KVh + kvh) * Ss];
    const float* __restrict__ pvb = &g_pv[(bb*KVh + kvh) * Ss * VBd];

    float l = 0.f;
    u64 acc2[16];
#pragma unroll
    for (int j = 0; j < 16; ++j) acc2[j] = 0ULL;

    const int row  = tid >> 2;
    const int part = tid & 3;

    for (int kt = 0; kt <= qt; ++kt) {
        const int t0 = kt * 64;
        *(float4*)&kx[row*KSTR + part*4] =
            *(const float4*)&pkb[(t0 + row)*QKBd + part*4];
        if (tid < 64) kx[tid*KSTR + 16] = skb[t0 + tid];
        *(float4*)&vx[row*VSTR + part*8] =
            *(const float4*)&pvb[(t0 + row)*VBd + part*8];
        *(float4*)&vx[row*VSTR + part*8 + 4] =
            *(const float4*)&pvb[(t0 + row)*VBd + part*8 + 4];
        __syncthreads();

        const bool bnd = (kt == qt);
#pragma unroll 4
        for (int i = 0; i < 16; ++i) {
            const int kk = sub + i*4;
            const ulonglong2* kr2 = (const ulonglong2*)&kx[kk * KSTR];
            ulonglong2 kA = kr2[0], kB = kr2[1], kC = kr2[2], kD = kr2[3];
            u64 d2 = fmul2(q2[0], kA.x);
            d2 = ffma2(q2[1], kA.y, d2);
            d2 = ffma2(q2[2], kB.x, d2);
            d2 = ffma2(q2[3], kB.y, d2);
            d2 = ffma2(q2[4], kC.x, d2);
            d2 = ffma2(q2[5], kC.y, d2);
            d2 = ffma2(q2[6], kD.x, d2);
            d2 = ffma2(q2[7], kD.y, d2);
            float2 df = unpk2(d2);
            const float x = fmaf(df.x + df.y, 2.f, -kx[kk*KSTR + 16]);
            float w = __expf(x);
            if (bnd && kk > ql) w = 0.f;        // causal mask (diag tile only)
            l += w;
            const u64 w2 = pack2(w, w);
            const ulonglong2* vr2 = (const ulonglong2*)&vx[kk * VSTR];
#pragma unroll
            for (int j = 0; j < 8; ++j) {
                ulonglong2 vv = vr2[j];
                acc2[2*j]   = ffma2(w2, vv.x, acc2[2*j]);
                acc2[2*j+1] = ffma2(w2, vv.y, acc2[2*j+1]);
            }
        }
        __syncthreads();
    }

    // reduce over the 4 sub-threads of each query
#pragma unroll
    for (int off = 1; off < 4; off <<= 1) {
        l += __shfl_xor_sync(0xffffffffu, l, off);
#pragma unroll
        for (int j = 0; j < 16; ++j)
            acc2[j] = fadd2(acc2[j], __shfl_xor_sync(0xffffffffu, acc2[j], off));
    }

    if (sub == 0) {
        const float invl = 1.f / l;
        float* orow = &g_vh[(bb*Ss + qg)*HVB + h*VBd];
#pragma unroll
        for (int j = 0; j < 8; ++j) {
            float2 p0 = unpk2(acc2[2*j]);
            float2 p1 = unpk2(acc2[2*j+1]);
            float4 o;
            o.x = p0.x * invl;
            o.y = p0.y * invl;
            o.z = p1.x * invl;
            o.w = p1.y * invl;
            *(float4*)&orow[j*4] = o;
        }
    }
}

// ---------------- Kernel 3: out = ((e1-e0) o vh) @ Wo + bias -----------------
__global__ __launch_bounds__(256) void out_kernel(
    const float* __restrict__ Wo, const float* __restrict__ e0,
    const float* __restrict__ e1, float* __restrict__ out)
{
    __shared__ u64   As[32 * 128];
    __shared__ float Bs[32 * BSTR];
    __shared__ float scs[HVB];

    const int m0  = blockIdx.x * 128;
    const int n0  = blockIdx.y * 64;
    const int tid = threadIdx.x;
    const int tm  = tid >> 4;
    const int tn  = tid & 15;
    const int fm  = tid >> 1;
    const int fk  = (tid & 1) * 16;
    const int bk  = tid >> 3;
    const int jb  = (tid & 7) * 8;

    scs[tid]       = e1[tid]       - e0[tid];
    scs[tid + 256] = e1[tid + 256] - e0[tid + 256];
    __syncthreads();   // REQUIRED: A-fill below reads scs written by other threads

    u64 acc[8][2];
#pragma unroll
    for (int i = 0; i < 8; ++i) { acc[i][0] = 0ULL; acc[i][1] = 0ULL; }

    for (int k0 = 0; k0 < HVB; k0 += 32) {
        {
            const float* Ar = &g_vh[(m0 + fm) * HVB + k0 + fk];
            float4 a0 = *(const float4*)(Ar + 0);
            float4 a1 = *(const float4*)(Ar + 4);
            float4 a2 = *(const float4*)(Ar + 8);
            float4 a3 = *(const float4*)(Ar + 12);
            float av[16] = {a0.x,a0.y,a0.z,a0.w, a1.x,a1.y,a1.z,a1.w,
                            a2.x,a2.y,a2.z,a2.w, a3.x,a3.y,a3.z,a3.w};
#pragma unroll
            for (int s = 0; s < 16; ++s) {
                const float v = av[s] * scs[k0 + fk + s];
                As[(fk + s) * 128 + fm] = pack2(v, v);
            }
        }
        {
            const float* Wr = &Wo[(k0 + bk) * Dd + n0 + jb];
            *(float4*)&Bs[bk * BSTR + jb]     = *(const float4*)(Wr + 0);
            *(float4*)&Bs[bk * BSTR + jb + 4] = *(const float4*)(Wr + 4);
        }
        __syncthreads();

#pragma unroll
        for (int k = 0; k < 32; ++k) {
            const ulonglong2* ap = (const ulonglong2*)&As[k * 128 + tm * 8];
            ulonglong2 a01 = ap[0], a23 = ap[1], a45 = ap[2], a67 = ap[3];
            ulonglong2 bv = *(const ulonglong2*)&Bs[k * BSTR + tn * 4];
            u64 ar[8] = {a01.x, a01.y, a23.x, a23.y, a45.x, a45.y, a67.x, a67.y};
#pragma unroll
            for (int i = 0; i < 8; ++i) {
                acc[i][0] = ffma2(ar[i], bv.x, acc[i][0]);
                acc[i][1] = ffma2(ar[i], bv.y, acc[i][1]);
            }
        }
        __syncthreads();
    }

    const int col0 = n0 + tn * 4;
    const float4 b4 = *(const float4*)&g_bias[col0];
#pragma unroll
    for (int i = 0; i < 8; ++i) {
        const int r = m0 + tm * 8 + i;
        float2 p0 = unpk2(acc[i][0]);
        float2 p1 = unpk2(acc[i][1]);
        float4 o;
        o.x = p0.x + b4.x;
        o.y = p0.y + b4.y;
        o.z = p1.x + b4.z;
        o.w = p1.y + b4.w;
        *(float4*)&out[r*Dd + col0] = o;
    }
}

// ---------------- launch -----------------------------------------------------
extern "C" void kernel_launch(void* const* d_in, const int* in_sizes, int n_in,
                              void* d_out, int out_size)
{
    const float* hs = (const float*)d_in[0];
    const float* Wq = (const float*)d_in[1];
    const float* Wk = (const float*)d_in[2];
    const float* Wv = (const float*)d_in[3];
    const float* Wo = (const float*)d_in[4];
    const float* e0 = (const float*)d_in[5];
    const float* e1 = (const float*)d_in[6];
    float* out = (float*)d_out;

    dim3 blk(256);
    proj_kernel<<<dim3(MROWS/128, 4), blk>>>(hs, Wq, Hh*QKBd, 0);   // Q
    proj_kernel<<<dim3(MROWS/128, 1), blk>>>(hs, Wk, KVh*QKBd, 1);  // K
    proj_kernel<<<dim3(MROWS/128, 2), blk>>>(hs, Wv, KVh*VBd, 2);   // V
    sk_kernel<<<(Bb*KVh*Ss)/256, 256>>>();
    bias_kernel<<<Dd/256, 256>>>(Wo, e0);
    attn_kernel<<<dim3(Ss/64, Hh, Bb), blk>>>();
    out_kernel<<<dim3(MROWS/128, Dd/64), blk>>>(Wo, e0, e1, out);
}

// round 6
// speedup vs baseline: 1.0563x; 1.0563x over previous
#include <cuda_runtime.h>

// Problem dims (fixed)
#define Bb   2
#define Ss   2048
#define Dd   1024
#define Hh   16
#define KVh  4
#define QKBd 16
#define VBd  32
#define MROWS (Bb*Ss)          // 4096
#define HVB   (Hh*VBd)         // 512

// ---------------- scratch (static device arrays; no allocation) -------------
__device__ __align__(16) float g_pq[Bb*Hh*Ss*QKBd];    // [(b*H+h)*S+s][16]
__device__ __align__(16) float g_pk[Bb*KVh*Ss*QKBd];   // [(b*KV+kv)*S+t][16]
__device__ __align__(16) float g_sk[Bb*KVh*Ss];        // row sums of pk
__device__ __align__(16) float g_pv[Bb*KVh*Ss*VBd];    // [(b*KV+kv)*S+t][32]
__device__ __align__(16) float g_vh[Bb*Ss*HVB];        // [b*S+s][h*32+j]
__device__ __align__(16) float g_bias[Dd];             // e0 @ Wo

__device__ __forceinline__ float sigmoidf_fast(float x) {
    return __fdividef(1.f, 1.f + __expf(-x));
}
__device__ __forceinline__ unsigned f2tf(float x) {
    unsigned u; asm("cvt.rna.tf32.f32 %0, %1;" : "=r"(u) : "f"(x)); return u;
}
__device__ __forceinline__ void mma_tf32(
    float& c0, float& c1, float& c2, float& c3,
    unsigned a0, unsigned a1, unsigned a2, unsigned a3,
    unsigned b0, unsigned b1)
{
    asm("mma.sync.aligned.m16n8k8.row.col.f32.tf32.tf32.f32 "
        "{%0,%1,%2,%3},{%4,%5,%6,%7},{%8,%9},{%0,%1,%2,%3};"
        : "+f"(c0), "+f"(c1), "+f"(c2), "+f"(c3)
        : "r"(a0), "r"(a1), "r"(a2), "r"(a3), "r"(b0), "r"(b1));
}

// Fragment-permuted smem layout (see R4 notes):
// A tile: 128x32, blocks (mTile, k8) of 128 u32; elem (r16,c8):
//   lane=((r&7)<<2)|(c&3), j=(r>>3)|(((c>>2)&1)<<1)
// B tile: 32x64, blocks (n8, k8) of 64 u32; elem (kr,nc):
//   lane=(nc<<2)|(kr&3), j=kr>>2

// ---------------- Kernel 1: fused QKV projection (tf32 3-term emulation) ----
__global__ __launch_bounds__(256) void proj_tf32(
    const float* __restrict__ A,
    const float* __restrict__ Wq, const float* __restrict__ Wk,
    const float* __restrict__ Wv)
{
    __shared__ unsigned AsH[4096];
    __shared__ unsigned AsL[4096];
    __shared__ unsigned BsH[2048];
    __shared__ unsigned BsL[2048];

    const int tid  = threadIdx.x;
    const int lane = tid & 31;
    const int warp = tid >> 5;
    const int warpM = warp & 3;
    const int warpN = warp >> 2;
    const int m0 = blockIdx.x * 128;

    const float* W; int N, n0g, mode;
    const int yb = blockIdx.y;
    if (yb < 4)       { W = Wq; N = 256; n0g = yb * 64;       mode = 0; }
    else if (yb == 4) { W = Wk; N = 64;  n0g = 0;             mode = 1; }
    else              { W = Wv; N = 128; n0g = (yb - 5) * 64; mode = 2; }

    float acc[2][4][4];
#pragma unroll
    for (int mt = 0; mt < 2; ++mt)
#pragma unroll
        for (int nt = 0; nt < 4; ++nt)
#pragma unroll
            for (int j = 0; j < 4; ++j) acc[mt][nt][j] = 0.f;

    const int ar  = tid >> 1;
    const int acb = (tid & 1) * 16;
    const int bkr = tid >> 3;
    const int bnb = (tid & 7) * 8;

    for (int k0 = 0; k0 < Dd; k0 += 32) {
        // ---- A fill (hi/lo split, fragment order) ----
        {
            const float* Ap = &A[(m0 + ar) * Dd + k0 + acb];
            float4 q0 = *(const float4*)(Ap + 0);
            float4 q1 = *(const float4*)(Ap + 4);
            float4 q2 = *(const float4*)(Ap + 8);
            float4 q3 = *(const float4*)(Ap + 12);
            float av[16] = {q0.x,q0.y,q0.z,q0.w, q1.x,q1.y,q1.z,q1.w,
                            q2.x,q2.y,q2.z,q2.w, q3.x,q3.y,q3.z,q3.w};
            const int r16 = ar & 15, mt = ar >> 4;
#pragma unroll
            for (int u = 0; u < 16; ++u) {
                const int c  = acb + u;
                const int k8 = c >> 3, c8 = c & 7;
                const int l2 = ((r16 & 7) << 2) | (c8 & 3);
                const int j  = (r16 >> 3) | (((c8 >> 2) & 1) << 1);
                const int idx = ((mt * 4 + k8) * 32 + l2) * 4 + j;
                const float x = av[u];
                const unsigned hb = f2tf(x);
                AsH[idx] = hb;
                AsL[idx] = f2tf(x - __uint_as_float(hb));
            }
        }
        // ---- B fill (hi/lo split, fragment order) ----
        {
            const float* Wp = &W[(k0 + bkr) * N + n0g + bnb];
            float4 w0 = *(const float4*)(Wp + 0);
            float4 w1 = *(const float4*)(Wp + 4);
            float wv[8] = {w0.x,w0.y,w0.z,w0.w, w1.x,w1.y,w1.z,w1.w};
            const int k8 = bkr >> 3, krr = bkr & 7;
#pragma unroll
            for (int u = 0; u < 8; ++u) {
                const int nc = bnb + u;
                const int n8t = nc >> 3, ncc = nc & 7;
                const int idx = ((n8t * 4 + k8) * 32 + ((ncc << 2) | (krr & 3))) * 2 + (krr >> 2);
                const float x = wv[u];
                const unsigned hb = f2tf(x);
                BsH[idx] = hb;
                BsL[idx] = f2tf(x - __uint_as_float(hb));
            }
        }
        __syncthreads();

#pragma unroll
        for (int k8 = 0; k8 < 4; ++k8) {
            uint2 bh[4], bl[4];
#pragma unroll
            for (int nt = 0; nt < 4; ++nt) {
                const int bi = (((warpN*4 + nt) * 4 + k8) * 32 + lane) * 2;
                bh[nt] = *(const uint2*)&BsH[bi];
                bl[nt] = *(const uint2*)&BsL[bi];
            }
#pragma unroll
            for (int mt = 0; mt < 2; ++mt) {
                const int base = (((warpM*2 + mt) * 4 + k8) * 32 + lane) * 4;
                uint4 ah = *(const uint4*)&AsH[base];
                uint4 al = *(const uint4*)&AsL[base];
#pragma unroll
                for (int nt = 0; nt < 4; ++nt) {
                    mma_tf32(acc[mt][nt][0], acc[mt][nt][1], acc[mt][nt][2], acc[mt][nt][3],
                             al.x, al.y, al.z, al.w, bh[nt].x, bh[nt].y);
                    mma_tf32(acc[mt][nt][0], acc[mt][nt][1], acc[mt][nt][2], acc[mt][nt][3],
                             ah.x, ah.y, ah.z, ah.w, bl[nt].x, bl[nt].y);
                    mma_tf32(acc[mt][nt][0], acc[mt][nt][1], acc[mt][nt][2], acc[mt][nt][3],
                             ah.x, ah.y, ah.z, ah.w, bh[nt].x, bh[nt].y);
                }
            }
        }
        __syncthreads();
    }

    // ---- epilogue: sigmoid + scatter ----
#pragma unroll
    for (int mt = 0; mt < 2; ++mt) {
#pragma unroll
        for (int nt = 0; nt < 4; ++nt) {
            const int c = n0g + warpN*32 + nt*8 + (lane & 3) * 2;
#pragma unroll
            for (int half = 0; half < 2; ++half) {
                const int r  = m0 + warpM*32 + mt*16 + (lane >> 2) + half*8;
                const int bb = r >> 11, ss = r & (Ss - 1);
                float2 v;
                v.x = sigmoidf_fast(acc[mt][nt][half*2 + 0]);
                v.y = sigmoidf_fast(acc[mt][nt][half*2 + 1]);
                if (mode == 0) {
                    const int h = c >> 4, d = c & 15;
                    *(float2*)&g_pq[(((bb*Hh + h)*Ss) + ss)*QKBd + d] = v;
                } else if (mode == 1) {
                    const int kv = c >> 4, d = c & 15;
                    *(float2*)&g_pk[(((bb*KVh + kv)*Ss) + ss)*QKBd + d] = v;
                } else {
                    const int kv = c >> 5, d = c & 31;
                    *(float2*)&g_pv[(((bb*KVh + kv)*Ss) + ss)*VBd + d] = v;
                }
            }
        }
    }
}

// ---------------- Kernel 1b: sk[t] = sum_d pk[t][d] --------------------------
__global__ void sk_kernel()
{
    const int idx = blockIdx.x * 256 + threadIdx.x;
    const float4* p = (const float4*)&g_pk[idx * QKBd];
    float4 a = p[0], b = p[1], c = p[2], d = p[3];
    g_sk[idx] = ((a.x + a.y) + (a.z + a.w)) + ((b.x + b.y) + (b.z + b.w))
              + ((c.x + c.y) + (c.z + c.w)) + ((d.x + d.y) + (d.z + d.w));
}

// ---------------- Kernel 1c: bias[d] = sum_j e0[j] * Wo[j][d] ----------------
__global__ void bias_kernel(const float* __restrict__ Wo, const float* __restrict__ e0)
{
    const int d = blockIdx.x * 256 + threadIdx.x;
    float s = 0.f;
    for (int j = 0; j < HVB; ++j)
        s = fmaf(e0[j], Wo[j * Dd + d], s);
    g_bias[d] = s;
}

// ---------------- Kernel 2: causal attention (fp32 scalar) -------------------
#define KSTR 20
#define VSTR 36

__global__ __launch_bounds__(256) void attn_kernel()
{
    __shared__ float kx[64 * KSTR];
    __shared__ float vx[64 * VSTR];
    const int qt  = (Ss/64 - 1) - blockIdx.x;   // heavy tiles first
    const int h   = blockIdx.y;
    const int bb  = blockIdx.z;
    const int kvh = h >> 2;
    const int tid = threadIdx.x;
    const int ql  = tid >> 2;
    const int sub = tid & 3;
    const int qg  = qt * 64 + ql;

    const float* __restrict__ pqr = &g_pq[((bb*Hh + h)*Ss + qg) * QKBd];
    const float4 qa = *(const float4*)&pqr[0];
    const float4 qb = *(const float4*)&pqr[4];
    const float4 qc = *(const float4*)&pqr[8];
    const float4 qd = *(const float4*)&pqr[12];

    const float* __restrict__ pkb = &g_pk[(bb*KVh + kvh) * Ss * QKBd];
    const float* __restrict__ skb = &g_sk[(bb*KVh + kvh) * Ss];
    const float* __restrict__ pvb = &g_pv[(bb*KVh + kvh) * Ss * VBd];

    float l = 0.f;
    float acc[VBd];
#pragma unroll
    for (int j = 0; j < VBd; ++j) acc[j] = 0.f;

    const int row  = tid >> 2;
    const int part = tid & 3;

    for (int kt = 0; kt <= qt; ++kt) {
        const int t0 = kt * 64;
        *(float4*)&kx[row*KSTR + part*4] =
            *(const float4*)&pkb[(t0 + row)*QKBd + part*4];
        if (tid < 64) kx[tid*KSTR + 16] = skb[t0 + tid];
        *(float4*)&vx[row*VSTR + part*8] =
            *(const float4*)&pvb[(t0 + row)*VBd + part*8];
        *(float4*)&vx[row*VSTR + part*8 + 4] =
            *(const float4*)&pvb[(t0 + row)*VBd + part*8 + 4];
        __syncthreads();

        const bool bnd = (kt == qt);
#pragma unroll 8
        for (int i = 0; i < 16; ++i) {
            const int kk = sub + i*4;
            const float* kr = &kx[kk * KSTR];
            const float4 k0 = *(const float4*)&kr[0];
            const float4 k1 = *(const float4*)&kr[4];
            const float4 k2 = *(const float4*)&kr[8];
            const float4 k3 = *(const float4*)&kr[12];
            float s0 = fmaf(k0.x,qa.x, fmaf(k0.y,qa.y, fmaf(k0.z,qa.z, k0.w*qa.w)));
            float s1 = fmaf(k1.x,qb.x, fmaf(k1.y,qb.y, fmaf(k1.z,qb.z, k1.w*qb.w)));
            float s2 = fmaf(k2.x,qc.x, fmaf(k2.y,qc.y, fmaf(k2.z,qc.z, k2.w*qc.w)));
            float s3 = fmaf(k3.x,qd.x, fmaf(k3.y,qd.y, fmaf(k3.z,qd.z, k3.w*qd.w)));
            const float dot = (s0 + s1) + (s2 + s3);
            const float x = fmaf(dot, 2.f, -kr[16]);
            float w = __expf(x);
            if (bnd && kk > ql) w = 0.f;
            l += w;
            const float* vr = &vx[kk * VSTR];
#pragma unroll
            for (int v4 = 0; v4 < 8; ++v4) {
                const float4 vv = *(const float4*)&vr[v4*4];
                acc[v4*4+0] = fmaf(w, vv.x, acc[v4*4+0]);
                acc[v4*4+1] = fmaf(w, vv.y, acc[v4*4+1]);
                acc[v4*4+2] = fmaf(w, vv.z, acc[v4*4+2]);
                acc[v4*4+3] = fmaf(w, vv.w, acc[v4*4+3]);
            }
        }
        __syncthreads();
    }

#pragma unroll
    for (int off = 1; off < 4; off <<= 1) {
        l += __shfl_xor_sync(0xffffffffu, l, off);
#pragma unroll
        for (int j = 0; j < VBd; ++j)
            acc[j] += __shfl_xor_sync(0xffffffffu, acc[j], off);
    }

    if (sub == 0) {
        const float invl = 1.f / l;
        float* orow = &g_vh[(bb*Ss + qg)*HVB + h*VBd];
#pragma unroll
        for (int v4 = 0; v4 < 8; ++v4) {
            float4 o;
            o.x = acc[v4*4+0] * invl;
            o.y = acc[v4*4+1] * invl;
            o.z = acc[v4*4+2] * invl;
            o.w = acc[v4*4+3] * invl;
            *(float4*)&orow[v4*4] = o;
        }
    }
}

// ---------------- Kernel 3: out = ((e1-e0) o vh) @ Wo + bias (tf32 3-term) ---
__global__ __launch_bounds__(256) void out_tf32(
    const float* __restrict__ Wo, const float* __restrict__ e0,
    const float* __restrict__ e1, float* __restrict__ out)
{
    __shared__ unsigned AsH[4096];
    __shared__ unsigned AsL[4096];
    __shared__ unsigned BsH[2048];
    __shared__ unsigned BsL[2048];
    __shared__ float scs[HVB];

    const int tid  = threadIdx.x;
    const int lane = tid & 31;
    const int warp = tid >> 5;
    const int warpM = warp & 3;
    const int warpN = warp >> 2;
    const int m0  = blockIdx.x * 128;
    const int n0g = blockIdx.y * 64;

    scs[tid]       = e1[tid]       - e0[tid];
    scs[tid + 256] = e1[tid + 256] - e0[tid + 256];
    __syncthreads();

    float acc[2][4][4];
#pragma unroll
    for (int mt = 0; mt < 2; ++mt)
#pragma unroll
        for (int nt = 0; nt < 4; ++nt)
#pragma unroll
            for (int j = 0; j < 4; ++j) acc[mt][nt][j] = 0.f;

    const int ar  = tid >> 1;
    const int acb = (tid & 1) * 16;
    const int bkr = tid >> 3;
    const int bnb = (tid & 7) * 8;

    for (int k0 = 0; k0 < HVB; k0 += 32) {
        {
            const float* Ap = &g_vh[(m0 + ar) * HVB + k0 + acb];
            float4 q0 = *(const float4*)(Ap + 0);
            float4 q1 = *(const float4*)(Ap + 4);
            float4 q2 = *(const float4*)(Ap + 8);
            float4 q3 = *(const float4*)(Ap + 12);
            float av[16] = {q0.x,q0.y,q0.z,q0.w, q1.x,q1.y,q1.z,q1.w,
                            q2.x,q2.y,q2.z,q2.w, q3.x,q3.y,q3.z,q3.w};
            const int r16 = ar & 15, mt = ar >> 4;
#pragma unroll
            for (int u = 0; u < 16; ++u) {
                const int c  = acb + u;
                const int k8 = c >> 3, c8 = c & 7;
                const int l2 = ((r16 & 7) << 2) | (c8 & 3);
                const int j  = (r16 >> 3) | (((c8 >> 2) & 1) << 1);
                const int idx = ((mt * 4 + k8) * 32 + l2) * 4 + j;
                const float x = av[u] * scs[k0 + c];
                const unsigned hb = f2tf(x);
                AsH[idx] = hb;
                AsL[idx] = f2tf(x - __uint_as_float(hb));
            }
        }
        {
            const float* Wp = &Wo[(k0 + bkr) * Dd + n0g + bnb];
            float4 w0 = *(const float4*)(Wp + 0);
            float4 w1 = *(const float4*)(Wp + 4);
            float wv[8] = {w0.x,w0.y,w0.z,w0.w, w1.x,w1.y,w1.z,w1.w};
            const int k8 = bkr >> 3, krr = bkr & 7;
#pragma unroll
            for (int u = 0; u < 8; ++u) {
                const int nc = bnb + u;
                const int n8t = nc >> 3, ncc = nc & 7;
                const int idx = ((n8t * 4 + k8) * 32 + ((ncc << 2) | (krr & 3))) * 2 + (krr >> 2);
                const float x = wv[u];
                const unsigned hb = f2tf(x);
                BsH[idx] = hb;
                BsL[idx] = f2tf(x - __uint_as_float(hb));
            }
        }
        __syncthreads();

#pragma unroll
        for (int k8 = 0; k8 < 4; ++k8) {
            uint2 bh[4], bl[4];
#pragma unroll
            for (int nt = 0; nt < 4; ++nt) {
                const int bi = (((warpN*4 + nt) * 4 + k8) * 32 + lane) * 2;
                bh[nt] = *(const uint2*)&BsH[bi];
                bl[nt] = *(const uint2*)&BsL[bi];
            }
#pragma unroll
            for (int mt = 0; mt < 2; ++mt) {
                const int base = (((warpM*2 + mt) * 4 + k8) * 32 + lane) * 4;
                uint4 ah = *(const uint4*)&AsH[base];
                uint4 al = *(const uint4*)&AsL[base];
#pragma unroll
                for (int nt = 0; nt < 4; ++nt) {
                    mma_tf32(acc[mt][nt][0], acc[mt][nt][1], acc[mt][nt][2], acc[mt][nt][3],
                             al.x, al.y, al.z, al.w, bh[nt].x, bh[nt].y);
                    mma_tf32(acc[mt][nt][0], acc[mt][nt][1], acc[mt][nt][2], acc[mt][nt][3],
                             ah.x, ah.y, ah.z, ah.w, bl[nt].x, bl[nt].y);
                    mma_tf32(acc[mt][nt][0], acc[mt][nt][1], acc[mt][nt][2], acc[mt][nt][3],
                             ah.x, ah.y, ah.z, ah.w, bh[nt].x, bh[nt].y);
                }
            }
        }
        __syncthreads();
    }

#pragma unroll
    for (int mt = 0; mt < 2; ++mt) {
#pragma unroll
        for (int nt = 0; nt < 4; ++nt) {
            const int c = n0g + warpN*32 + nt*8 + (lane & 3) * 2;
            const float2 bv = *(const float2*)&g_bias[c];
#pragma unroll
            for (int half = 0; half < 2; ++half) {
                const int r = m0 + warpM*32 + mt*16 + (lane >> 2) + half*8;
                float2 v;
                v.x = acc[mt][nt][half*2 + 0] + bv.x;
                v.y = acc[mt][nt][half*2 + 1] + bv.y;
                *(float2*)&out[r*Dd + c] = v;
            }
        }
    }
}

// ---------------- launch -----------------------------------------------------
extern "C" void kernel_launch(void* const* d_in, const int* in_sizes, int n_in,
                              void* d_out, int out_size)
{
    const float* hs = (const float*)d_in[0];
    const float* Wq = (const float*)d_in[1];
    const float* Wk = (const float*)d_in[2];
    const float* Wv = (const float*)d_in[3];
    const float* Wo = (const float*)d_in[4];
    const float* e0 = (const float*)d_in[5];
    const float* e1 = (const float*)d_in[6];
    float* out = (float*)d_out;

    dim3 blk(256);
    proj_tf32<<<dim3(MROWS/128, 7), blk>>>(hs, Wq, Wk, Wv);
    sk_kernel<<<(Bb*KVh*Ss)/256, 256>>>();
    bias_kernel<<<Dd/256, 256>>>(Wo, e0);
    attn_kernel<<<dim3(Ss/64, Hh, Bb), blk>>>();
    out_tf32<<<dim3(MROWS/128, Dd/64), blk>>>(Wo, e0, e1, out);
}

// round 10
// speedup vs baseline: 1.4772x; 1.3984x over previous
#include <cuda_runtime.h>

// Problem dims (fixed)
#define Bb   2
#define Ss   2048
#define Dd   1024
#define Hh   16
#define KVh  4
#define QKBd 16
#define VBd  32
#define MROWS (Bb*Ss)          // 4096
#define HVB   (Hh*VBd)         // 512

// ---------------- scratch (static device arrays; no allocation) -------------
__device__ __align__(16) float g_pq[Bb*Hh*Ss*QKBd];    // [(b*H+h)*S+s][16]
__device__ __align__(16) float g_pk[Bb*KVh*Ss*QKBd];   // [(b*KV+kv)*S+t][16]
__device__ __align__(16) float g_sk[Bb*KVh*Ss];        // row sums of pk
__device__ __align__(16) float g_pv[Bb*KVh*Ss*VBd];    // [(b*KV+kv)*S+t][32]
__device__ __align__(16) float g_vh[Bb*Ss*HVB];        // [b*S+s][h*32+j]
__device__ __align__(16) float g_bias[Dd];             // e0 @ Wo

__device__ __forceinline__ float sigmoidf_fast(float x) {
    return __fdividef(1.f, 1.f + __expf(-x));
}
__device__ __forceinline__ unsigned f2tf(float x) {
    unsigned u; asm("cvt.rna.tf32.f32 %0, %1;" : "=r"(u) : "f"(x)); return u;
}
__device__ __forceinline__ void mma_tf32(
    float& c0, float& c1, float& c2, float& c3,
    unsigned a0, unsigned a1, unsigned a2, unsigned a3,
    unsigned b0, unsigned b1)
{
    asm("mma.sync.aligned.m16n8k8.row.col.f32.tf32.tf32.f32 "
        "{%0,%1,%2,%3},{%4,%5,%6,%7},{%8,%9},{%0,%1,%2,%3};"
        : "+f"(c0), "+f"(c1), "+f"(c2), "+f"(c3)
        : "r"(a0), "r"(a1), "r"(a2), "r"(a3), "r"(b0), "r"(b1));
}

// Fragment-permuted smem layout:
// A tile: blocks of 128 u32; elem (r16,c8): lane=((r&7)<<2)|(c&3), j=(r>>3)|(((c>>2)&1)<<1)
// B tile: blocks of 64 u32;  elem (kr,nc):  lane=(nc<<2)|(kr&3), j=kr>>2

// ---------------- Kernel 1: fused QKV projection (tf32 3-term emulation) ----
__global__ __launch_bounds__(256) void proj_tf32(
    const float* __restrict__ A,
    const float* __restrict__ Wq, const float* __restrict__ Wk,
    const float* __restrict__ Wv)
{
    __shared__ unsigned AsH[4096];
    __shared__ unsigned AsL[4096];
    __shared__ unsigned BsH[2048];
    __shared__ unsigned BsL[2048];

    const int tid  = threadIdx.x;
    const int lane = tid & 31;
    const int warp = tid >> 5;
    const int warpM = warp & 3;
    const int warpN = warp >> 2;
    const int m0 = blockIdx.x * 128;

    const float* W; int N, n0g, mode;
    const int yb = blockIdx.y;
    if (yb < 4)       { W = Wq; N = 256; n0g = yb * 64;       mode = 0; }
    else if (yb == 4) { W = Wk; N = 64;  n0g = 0;             mode = 1; }
    else              { W = Wv; N = 128; n0g = (yb - 5) * 64; mode = 2; }

    float acc[2][4][4];
#pragma unroll
    for (int mt = 0; mt < 2; ++mt)
#pragma unroll
        for (int nt = 0; nt < 4; ++nt)
#pragma unroll
            for (int j = 0; j < 4; ++j) acc[mt][nt][j] = 0.f;

    const int ar  = tid >> 1;
    const int acb = (tid & 1) * 16;
    const int bkr = tid >> 3;
    const int bnb = (tid & 7) * 8;

    for (int k0 = 0; k0 < Dd; k0 += 32) {
        {
            const float* Ap = &A[(m0 + ar) * Dd + k0 + acb];
            float4 q0 = *(const float4*)(Ap + 0);
            float4 q1 = *(const float4*)(Ap + 4);
            float4 q2 = *(const float4*)(Ap + 8);
            float4 q3 = *(const float4*)(Ap + 12);
            float av[16] = {q0.x,q0.y,q0.z,q0.w, q1.x,q1.y,q1.z,q1.w,
                            q2.x,q2.y,q2.z,q2.w, q3.x,q3.y,q3.z,q3.w};
            const int r16 = ar & 15, mt = ar >> 4;
#pragma unroll
            for (int u = 0; u < 16; ++u) {
                const int c  = acb + u;
                const int k8 = c >> 3, c8 = c & 7;
                const int l2 = ((r16 & 7) << 2) | (c8 & 3);
                const int j  = (r16 >> 3) | (((c8 >> 2) & 1) << 1);
                const int idx = ((mt * 4 + k8) * 32 + l2) * 4 + j;
                const float x = av[u];
                const unsigned hb = f2tf(x);
                AsH[idx] = hb;
                AsL[idx] = f2tf(x - __uint_as_float(hb));
            }
        }
        {
            const float* Wp = &W[(k0 + bkr) * N + n0g + bnb];
            float4 w0 = *(const float4*)(Wp + 0);
            float4 w1 = *(const float4*)(Wp + 4);
            float wv[8] = {w0.x,w0.y,w0.z,w0.w, w1.x,w1.y,w1.z,w1.w};
            const int k8 = bkr >> 3, krr = bkr & 7;
#pragma unroll
            for (int u = 0; u < 8; ++u) {
                const int nc = bnb + u;
                const int n8t = nc >> 3, ncc = nc & 7;
                const int idx = ((n8t * 4 + k8) * 32 + ((ncc << 2) | (krr & 3))) * 2 + (krr >> 2);
                const float x = wv[u];
                const unsigned hb = f2tf(x);
                BsH[idx] = hb;
                BsL[idx] = f2tf(x - __uint_as_float(hb));
            }
        }
        __syncthreads();

#pragma unroll
        for (int k8 = 0; k8 < 4; ++k8) {
            uint2 bh[4], bl[4];
#pragma unroll
            for (int nt = 0; nt < 4; ++nt) {
                const int bi = (((warpN*4 + nt) * 4 + k8) * 32 + lane) * 2;
                bh[nt] = *(const uint2*)&BsH[bi];
                bl[nt] = *(const uint2*)&BsL[bi];
            }
#pragma unroll
            for (int mt = 0; mt < 2; ++mt) {
                const int base = (((warpM*2 + mt) * 4 + k8) * 32 + lane) * 4;
                uint4 ah = *(const uint4*)&AsH[base];
                uint4 al = *(const uint4*)&AsL[base];
#pragma unroll
                for (int nt = 0; nt < 4; ++nt) {
                    mma_tf32(acc[mt][nt][0], acc[mt][nt][1], acc[mt][nt][2], acc[mt][nt][3],
                             al.x, al.y, al.z, al.w, bh[nt].x, bh[nt].y);
                    mma_tf32(acc[mt][nt][0], acc[mt][nt][1], acc[mt][nt][2], acc[mt][nt][3],
                             ah.x, ah.y, ah.z, ah.w, bl[nt].x, bl[nt].y);
                    mma_tf32(acc[mt][nt][0], acc[mt][nt][1], acc[mt][nt][2], acc[mt][nt][3],
                             ah.x, ah.y, ah.z, ah.w, bh[nt].x, bh[nt].y);
                }
            }
        }
        __syncthreads();
    }

#pragma unroll
    for (int mt = 0; mt < 2; ++mt) {
#pragma unroll
        for (int nt = 0; nt < 4; ++nt) {
            const int c = n0g + warpN*32 + nt*8 + (lane & 3) * 2;
#pragma unroll
            for (int half = 0; half < 2; ++half) {
                const int r  = m0 + warpM*32 + mt*16 + (lane >> 2) + half*8;
                const int bb = r >> 11, ss = r & (Ss - 1);
                float2 v;
                v.x = sigmoidf_fast(acc[mt][nt][half*2 + 0]);
                v.y = sigmoidf_fast(acc[mt][nt][half*2 + 1]);
                if (mode == 0) {
                    const int h = c >> 4, d = c & 15;
                    *(float2*)&g_pq[(((bb*Hh + h)*Ss) + ss)*QKBd + d] = v;
                } else if (mode == 1) {
                    const int kv = c >> 4, d = c & 15;
                    *(float2*)&g_pk[(((bb*KVh + kv)*Ss) + ss)*QKBd + d] = v;
                } else {
                    const int kv = c >> 5, d = c & 31;
                    *(float2*)&g_pv[(((bb*KVh + kv)*Ss) + ss)*VBd + d] = v;
                }
            }
        }
    }
}

// ---------------- Kernel 1b: sk[t] = sum_d pk[t][d] --------------------------
__global__ void sk_kernel()
{
    const int idx = blockIdx.x * 256 + threadIdx.x;
    const float4* p = (const float4*)&g_pk[idx * QKBd];
    float4 a = p[0], b = p[1], c = p[2], d = p[3];
    g_sk[idx] = ((a.x + a.y) + (a.z + a.w)) + ((b.x + b.y) + (b.z + b.w))
              + ((c.x + c.y) + (c.z + c.w)) + ((d.x + d.y) + (d.z + d.w));
}

// ---------------- Kernel 1c: bias[d] = sum_j e0[j] * Wo[j][d] ----------------
__global__ void bias_kernel(const float* __restrict__ Wo, const float* __restrict__ e0)
{
    const int d = blockIdx.x * 256 + threadIdx.x;
    float s = 0.f;
    for (int j = 0; j < HVB; ++j)
        s = fmaf(e0[j], Wo[j * Dd + d], s);
    g_bias[d] = s;
}

// ---------------- Kernel 2: causal flash attention (tf32 MMA, 3-term) --------
// S = (2*Q)·K^T - sk ; P = exp(S) (no max needed: bounded logits) ;
// O = P·V / rowsum(P).
// Block = 128 threads (4 warps). Block tile: 64 queries; warp w owns 16.
// Per 64-key tile: K,V staged in smem as hi/lo B-fragments; per 8-key slab:
// 6 S-MMAs -> exp/mask -> shfl C->A frag -> split -> 12 PV-MMAs.
__global__ __launch_bounds__(128) void attn_mma()
{
    __shared__ unsigned Ksh[1024], Ksl[1024];   // 8 n8 x 2 k8 x 64
    __shared__ unsigned Vsh[2048], Vsl[2048];   // 4 n8 x 8 k8 x 64
    __shared__ float    sks[64];

    const int qt   = (Ss/64 - 1) - blockIdx.x;   // heavy tiles first
    const int h    = blockIdx.y;
    const int bb   = blockIdx.z;
    const int kvh  = h >> 2;
    const int tid  = threadIdx.x;
    const int lane = tid & 31;
    const int w    = tid >> 5;
    const int q0   = qt * 64;
    const int r    = lane >> 2;
    const int c4   = lane & 3;

    const float* __restrict__ pqb = &g_pq[((bb*Hh + h)*Ss) * QKBd];
    const float* __restrict__ pkb = &g_pk[(bb*KVh + kvh) * Ss * QKBd];
    const float* __restrict__ skb = &g_sk[(bb*KVh + kvh) * Ss];
    const float* __restrict__ pvb = &g_pv[(bb*KVh + kvh) * Ss * VBd];

    // ---- Q fragments (pre-scaled by 2, hi/lo split) ----
    unsigned aqh[2][4], aql[2][4];
    const int qrow0 = q0 + w*16 + r;
#pragma unroll
    for (int k8 = 0; k8 < 2; ++k8) {
#pragma unroll
        for (int j = 0; j < 4; ++j) {
            const int row = qrow0 + ((j & 1) ? 8 : 0);
            const int col = k8*8 + c4 + ((j & 2) ? 4 : 0);
            const float x = 2.f * pqb[row*QKBd + col];
            const unsigned hb = f2tf(x);
            aqh[k8][j] = hb;
            aql[k8][j] = f2tf(x - __uint_as_float(hb));
        }
    }

    float o[4][4];
#pragma unroll
    for (int ntv = 0; ntv < 4; ++ntv)
#pragma unroll
        for (int j = 0; j < 4; ++j) o[ntv][j] = 0.f;
    float lr = 0.f, lr8 = 0.f;

    for (int kt = 0; kt <= qt; ++kt) {
        const int t0 = kt * 64;

        // ---- fill K (hi/lo, B-frag layout) ----
        {
            const int key = tid >> 1, cb = (tid & 1) * 8;
            const float* kp = &pkb[(t0 + key)*QKBd + cb];
            float4 v0 = *(const float4*)(kp + 0);
            float4 v1 = *(const float4*)(kp + 4);
            float kv[8] = {v0.x,v0.y,v0.z,v0.w, v1.x,v1.y,v1.z,v1.w};
            const int n8t = key >> 3, nc = key & 7;
#pragma unroll
            for (int u = 0; u < 8; ++u) {
                const int bit = cb + u;
                const int k8 = bit >> 3, kr = bit & 7;
                const int idx = ((n8t*2 + k8)*32 + ((nc << 2) | (kr & 3)))*2 + (kr >> 2);
                const float x = kv[u];
                const unsigned hb = f2tf(x);
                Ksh[idx] = hb;
                Ksl[idx] = f2tf(x - __uint_as_float(hb));
            }
        }
        if (tid < 64) sks[tid] = skb[t0 + tid];
        // ---- fill V (hi/lo, B-frag layout) ----
        {
            const int key = tid >> 1, db = (tid & 1) * 16;
            const float* vp = &pvb[(t0 + key)*VBd + db];
            float4 a0 = *(const float4*)(vp + 0);
            float4 a1 = *(const float4*)(vp + 4);
            float4 a2 = *(const float4*)(vp + 8);
            float4 a3 = *(const float4*)(vp + 12);
            float vv[16] = {a0.x,a0.y,a0.z,a0.w, a1.x,a1.y,a1.z,a1.w,
                            a2.x,a2.y,a2.z,a2.w, a3.x,a3.y,a3.z,a3.w};
            const int k8 = key >> 3, kr = key & 7;
#pragma unroll
            for (int u = 0; u < 16; ++u) {
                const int d = db + u;
                const int n8t = d >> 3, nc = d & 7;
                const int idx = (n8t*8 + k8)*64 + ((nc << 2) | (kr & 3))*2 + (kr >> 2);
                const float x = vv[u];
                const unsigned hb = f2tf(x);
                Vsh[idx] = hb;
                Vsl[idx] = f2tf(x - __uint_as_float(hb));
            }
        }
        __syncthreads();

        const bool diag = (kt == qt);
        const int ntmax = diag ? (w*2 + 2) : 8;
        for (int nt = 0; nt < ntmax; ++nt) {
            // ---- S = 2*Q . K^T (3-term) ----
            float s0 = 0.f, s1 = 0.f, s2 = 0.f, s3 = 0.f;
#pragma unroll
            for (int k8 = 0; k8 < 2; ++k8) {
                const int bi = ((nt*2 + k8)*32 + lane)*2;
                uint2 bh = *(const uint2*)&Ksh[bi];
                uint2 bl = *(const uint2*)&Ksl[bi];
                mma_tf32(s0,s1,s2,s3, aql[k8][0],aql[k8][1],aql[k8][2],aql[k8][3], bh.x, bh.y);
                mma_tf32(s0,s1,s2,s3, aqh[k8][0],aqh[k8][1],aqh[k8][2],aqh[k8][3], bl.x, bl.y);
                mma_tf32(s0,s1,s2,s3, aqh[k8][0],aqh[k8][1],aqh[k8][2],aqh[k8][3], bh.x, bh.y);
            }
            const float2 skp = *(const float2*)&sks[nt*8 + c4*2];
            float e0 = __expf(s0 - skp.x);
            float e1 = __expf(s1 - skp.y);
            float e2 = __expf(s2 - skp.x);
            float e3 = __expf(s3 - skp.y);
            if (diag) {
                const int keyb = nt*8 + c4*2;    // local key (t0 == q0)
                const int ql0  = w*16 + r;       // local query row r
                if (keyb     > ql0)     e0 = 0.f;
                if (keyb + 1 > ql0)     e1 = 0.f;
                if (keyb     > ql0 + 8) e2 = 0.f;
                if (keyb + 1 > ql0 + 8) e3 = 0.f;
            }
            lr  += e0 + e1;
            lr8 += e2 + e3;

            // ---- C-frag -> A-frag via shuffles ----
            const int ls  = (lane & ~3) | (c4 >> 1);
            const int ls2 = ls + 2;
            const float t00 = __shfl_sync(0xffffffffu, e0, ls);
            const float t01 = __shfl_sync(0xffffffffu, e1, ls);
            const float t10 = __shfl_sync(0xffffffffu, e2, ls);
            const float t11 = __shfl_sync(0xffffffffu, e3, ls);
            const float u00 = __shfl_sync(0xffffffffu, e0, ls2);
            const float u01 = __shfl_sync(0xffffffffu, e1, ls2);
            const float u10 = __shfl_sync(0xffffffffu, e2, ls2);
            const float u11 = __shfl_sync(0xffffffffu, e3, ls2);
            const bool odd = (c4 & 1);
            const float p0 = odd ? t01 : t00;   // (r,    key c4)
            const float p1 = odd ? t11 : t10;   // (r+8,  key c4)
            const float p2 = odd ? u01 : u00;   // (r,    key c4+4)
            const float p3 = odd ? u11 : u10;   // (r+8,  key c4+4)
            unsigned ph[4], pl[4];
            {
                const float pv[4] = {p0, p1, p2, p3};
#pragma unroll
                for (int j = 0; j < 4; ++j) {
                    const unsigned hb = f2tf(pv[j]);
                    ph[j] = hb;
                    pl[j] = f2tf(pv[j] - __uint_as_float(hb));
                }
            }

            // ---- O += P . V (3-term) ----
#pragma unroll
            for (int ntv = 0; ntv < 4; ++ntv) {
                const int bi = (ntv*8 + nt)*64 + lane*2;
                uint2 bh = *(const uint2*)&Vsh[bi];
                uint2 bl = *(const uint2*)&Vsl[bi];
                mma_tf32(o[ntv][0],o[ntv][1],o[ntv][2],o[ntv][3],
                         pl[0],pl[1],pl[2],pl[3], bh.x, bh.y);
                mma_tf32(o[ntv][0],o[ntv][1],o[ntv][2],o[ntv][3],
                         ph[0],ph[1],ph[2],ph[3], bl.x, bl.y);
                mma_tf32(o[ntv][0],o[ntv][1],o[ntv][2],o[ntv][3],
                         ph[0],ph[1],ph[2],ph[3], bh.x, bh.y);
            }
        }
        __syncthreads();
    }

    // ---- normalize + write ----
    lr  += __shfl_xor_sync(0xffffffffu, lr, 1);
    lr  += __shfl_xor_sync(0xffffffffu, lr, 2);
    lr8 += __shfl_xor_sync(0xffffffffu, lr8, 1);
    lr8 += __shfl_xor_sync(0xffffffffu, lr8, 2);
    const float ir  = 1.f / lr;
    const float ir8 = 1.f / lr8;

    float* orow0 = &g_vh[(bb*Ss + qrow0) * HVB + h*VBd];
    float* orow8 = orow0 + 8 * HVB;
#pragma unroll
    for (int ntv = 0; ntv < 4; ++ntv) {
        const int d0 = ntv*8 + c4*2;
        float2 v0; v0.x = o[ntv][0] * ir;  v0.y = o[ntv][1] * ir;
        float2 v8; v8.x = o[ntv][2] * ir8; v8.y = o[ntv][3] * ir8;
        *(float2*)&orow0[d0] = v0;
        *(float2*)&orow8[d0] = v8;
    }
}

// ---------------- Kernel 3: out = ((e1-e0) o vh) @ Wo + bias (tf32 3-term) ---
__global__ __launch_bounds__(256) void out_tf32(
    const float* __restrict__ Wo, const float* __restrict__ e0,
    const float* __restrict__ e1, float* __restrict__ out)
{
    __shared__ unsigned AsH[4096];
    __shared__ unsigned AsL[4096];
    __shared__ unsigned BsH[2048];
    __shared__ unsigned BsL[2048];
    __shared__ float scs[HVB];

    const int tid  = threadIdx.x;
    const int lane = tid & 31;
    const int warp = tid >> 5;
    const int warpM = warp & 3;
    const int warpN = warp >> 2;
    const int m0  = blockIdx.x * 128;
    const int n0g = blockIdx.y * 64;

    scs[tid]       = e1[tid]       - e0[tid];
    scs[tid + 256] = e1[tid + 256] - e0[tid + 256];
    __syncthreads();

    float acc[2][4][4];
#pragma unroll
    for (int mt = 0; mt < 2; ++mt)
#pragma unroll
        for (int nt = 0; nt < 4; ++nt)
#pragma unroll
            for (int j = 0; j < 4; ++j) acc[mt][nt][j] = 0.f;

    const int ar  = tid >> 1;
    const int acb = (tid & 1) * 16;
    const int bkr = tid >> 3;
    const int bnb = (tid & 7) * 8;

    for (int k0 = 0; k0 < HVB; k0 += 32) {
        {
            const float* Ap = &g_vh[(m0 + ar) * HVB + k0 + acb];
            float4 q0 = *(const float4*)(Ap + 0);
            float4 q1 = *(const float4*)(Ap + 4);
            float4 q2 = *(const float4*)(Ap + 8);
            float4 q3 = *(const float4*)(Ap + 12);
            float av[16] = {q0.x,q0.y,q0.z,q0.w, q1.x,q1.y,q1.z,q1.w,
                            q2.x,q2.y,q2.z,q2.w, q3.x,q3.y,q3.z,q3.w};
            const int r16 = ar & 15, mt = ar >> 4;
#pragma unroll
            for (int u = 0; u < 16; ++u) {
                const int c  = acb + u;
                const int k8 = c >> 3, c8 = c & 7;
                const int l2 = ((r16 & 7) << 2) | (c8 & 3);
                const int j  = (r16 >> 3) | (((c8 >> 2) & 1) << 1);
                const int idx = ((mt * 4 + k8) * 32 + l2) * 4 + j;
                const float x = av[u] * scs[k0 + c];
                const unsigned hb = f2tf(x);
                AsH[idx] = hb;
                AsL[idx] = f2tf(x - __uint_as_float(hb));
            }
        }
        {
            const float* Wp = &Wo[(k0 + bkr) * Dd + n0g + bnb];
            float4 w0 = *(const float4*)(Wp + 0);
            float4 w1 = *(const float4*)(Wp + 4);
            float wv[8] = {w0.x,w0.y,w0.z,w0.w, w1.x,w1.y,w1.z,w1.w};
            const int k8 = bkr >> 3, krr = bkr & 7;
#pragma unroll
            for (int u = 0; u < 8; ++u) {
                const int nc = bnb + u;
                const int n8t = nc >> 3, ncc = nc & 7;
                const int idx = ((n8t * 4 + k8) * 32 + ((ncc << 2) | (krr & 3))) * 2 + (krr >> 2);
                const float x = wv[u];
                const unsigned hb = f2tf(x);
                BsH[idx] = hb;
                BsL[idx] = f2tf(x - __uint_as_float(hb));
            }
        }
        __syncthreads();

#pragma unroll
        for (int k8 = 0; k8 < 4; ++k8) {
            uint2 bh[4], bl[4];
#pragma unroll
            for (int nt = 0; nt < 4; ++nt) {
                const int bi = (((warpN*4 + nt) * 4 + k8) * 32 + lane) * 2;
                bh[nt] = *(const uint2*)&BsH[bi];
                bl[nt] = *(const uint2*)&BsL[bi];
            }
#pragma unroll
            for (int mt = 0; mt < 2; ++mt) {
                const int base = (((warpM*2 + mt) * 4 + k8) * 32 + lane) * 4;
                uint4 ah = *(const uint4*)&AsH[base];
                uint4 al = *(const uint4*)&AsL[base];
#pragma unroll
                for (int nt = 0; nt < 4; ++nt) {
                    mma_tf32(acc[mt][nt][0], acc[mt][nt][1], acc[mt][nt][2], acc[mt][nt][3],
                             al.x, al.y, al.z, al.w, bh[nt].x, bh[nt].y);
                    mma_tf32(acc[mt][nt][0], acc[mt][nt][1], acc[mt][nt][2], acc[mt][nt][3],
                             ah.x, ah.y, ah.z, ah.w, bl[nt].x, bl[nt].y);
                    mma_tf32(acc[mt][nt][0], acc[mt][nt][1], acc[mt][nt][2], acc[mt][nt][3],
                             ah.x, ah.y, ah.z, ah.w, bh[nt].x, bh[nt].y);
                }
            }
        }
        __syncthreads();
    }

#pragma unroll
    for (int mt = 0; mt < 2; ++mt) {
#pragma unroll
        for (int nt = 0; nt < 4; ++nt) {
            const int c = n0g + warpN*32 + nt*8 + (lane & 3) * 2;
            const float2 bv = *(const float2*)&g_bias[c];
#pragma unroll
            for (int half = 0; half < 2; ++half) {
                const int r = m0 + warpM*32 + mt*16 + (lane >> 2) + half*8;
                float2 v;
                v.x = acc[mt][nt][half*2 + 0] + bv.x;
                v.y = acc[mt][nt][half*2 + 1] + bv.y;
                *(float2*)&out[r*Dd + c] = v;
            }
        }
    }
}

// ---------------- launch -----------------------------------------------------
extern "C" void kernel_launch(void* const* d_in, const int* in_sizes, int n_in,
                              void* d_out, int out_size)
{
    const float* hs = (const float*)d_in[0];
    const float* Wq = (const float*)d_in[1];
    const float* Wk = (const float*)d_in[2];
    const float* Wv = (const float*)d_in[3];
    const float* Wo = (const float*)d_in[4];
    const float* e0 = (const float*)d_in[5];
    const float* e1 = (const float*)d_in[6];
    float* out = (float*)d_out;

    proj_tf32<<<dim3(MROWS/128, 7), 256>>>(hs, Wq, Wk, Wv);
    sk_kernel<<<(Bb*KVh*Ss)/256, 256>>>();
    bias_kernel<<<Dd/256, 256>>>(Wo, e0);
    attn_mma<<<dim3(Ss/64, Hh, Bb), 128>>>();
    out_tf32<<<dim3(MROWS/128, Dd/64), 256>>>(Wo, e0, e1, out);
}